// round 8
// baseline (speedup 1.0000x reference)
#include <cuda_runtime.h>
#include <cuda_fp16.h>

#define B_ 16
#define O_ 32
#define CPO_ 4
#define H_ 128
#define W_ 128
#define S_ 16
#define T_ 32
#define HW_ (H_*W_)
#define NT_ ((B_*O_*H_*W_/4)/256)   /* transpose blocks = 8192 */
#define ROWB_ (W_/2*16)             /* bytes per scratch row = 1024 */

typedef unsigned long long ull;

// Scratch: transposed input, (B,O,H,W/2) uint4 = 2 adjacent pixels x 4ch fp16.
__device__ uint4 g_xT4[(size_t)B_ * O_ * H_ * W_ / 2];
__device__ int2  g_shift[O_ * S_];
__device__ uint4 g_wtsh[O_ * S_];
// Zero page: OOB pointers redirect here; sized for +4*ROWB_+16 byte offsets.
__device__ uint4 g_zero[4 * 64 + 8];   // 4224 B, zero-initialized

// ---------------------------------------------------------------------------
// packed helpers
// ---------------------------------------------------------------------------
__device__ __forceinline__ void add2(ull& d, ull v) {
    asm("add.rn.f32x2 %0,%0,%1;" : "+l"(d) : "l"(v));
}
__device__ __forceinline__ void unpk(ull v, float& lo, float& hi) {
    asm("mov.b64 {%0,%1},%2;" : "=f"(lo), "=f"(hi) : "l"(v));
}
__device__ __forceinline__ ull h2f2(unsigned u) {
    ull r;
    asm("{\n\t.reg .b16 a,b;\n\t.reg .f32 lo,hi;\n\t"
        "mov.b32 {a,b},%1;\n\tcvt.f32.f16 lo,a;\n\tcvt.f32.f16 hi,b;\n\t"
        "mov.b64 %0,{lo,hi};\n\t}" : "=l"(r) : "r"(u));
    return r;
}
__device__ __forceinline__ __half2 u2h(unsigned u) {
    return *reinterpret_cast<__half2*>(&u);
}
__device__ __forceinline__ unsigned h2u(__half2 h) {
    return *reinterpret_cast<unsigned*>(&h);
}

// ---------------------------------------------------------------------------
// Kernel 1 (fused): blocks [0,NT_) transpose, blocks [NT_,NT_+4) params.
// ---------------------------------------------------------------------------
__global__ void pre_kernel(const float* __restrict__ x,
                           const float* __restrict__ ox, const float* __restrict__ oy,
                           const float* __restrict__ ua, const float* __restrict__ us,
                           const float* __restrict__ ar, const float* __restrict__ sr)
{
    if (blockIdx.x < NT_) {
        int idx  = blockIdx.x * 256 + threadIdx.x;      // pixel-group of 4
        int wg   = idx & (W_/4 - 1);
        int rest = idx >> 5;                            // bo*H + h
        size_t base = ((size_t)(rest >> 7) * CPO_ * H_ + (rest & (H_-1))) * W_ + wg * 4;

        float4 c0 = *(const float4*)(x + base);
        float4 c1 = *(const float4*)(x + base + HW_);
        float4 c2 = *(const float4*)(x + base + 2 * HW_);
        float4 c3 = *(const float4*)(x + base + 3 * HW_);

        uint4 o0, o1;
        __half2 h;
        h = __floats2half2_rn(c0.x, c1.x); o0.x = h2u(h);
        h = __floats2half2_rn(c2.x, c3.x); o0.y = h2u(h);
        h = __floats2half2_rn(c0.y, c1.y); o0.z = h2u(h);
        h = __floats2half2_rn(c2.y, c3.y); o0.w = h2u(h);
        h = __floats2half2_rn(c0.z, c1.z); o1.x = h2u(h);
        h = __floats2half2_rn(c2.z, c3.z); o1.y = h2u(h);
        h = __floats2half2_rn(c0.w, c1.w); o1.z = h2u(h);
        h = __floats2half2_rn(c2.w, c3.w); o1.w = h2u(h);

        g_xT4[(size_t)idx * 2]     = o0;
        g_xT4[(size_t)idx * 2 + 1] = o1;
        return;
    }

    // ---- param path ----
    const int lane = threadIdx.x & 31;
    const int o    = (blockIdx.x - NT_) * 8 + (threadIdx.x >> 5);
    const float MINA = 0.024979197860971382f;
    const float PIF  = 3.14159265358979323846f;
    const float EPSF = 1.1920928955078125e-07f;

    float astd = 1.f / (1.f + expf(-ar[o])) * (PIF - MINA) + MINA;
    float sstd = 1.f / (1.f + expf(-sr[o])) * (5.0f - 0.2f) + 0.2f;
    float high_a = fminf(astd * 3.f, PIF);
    float s3 = sstd * 3.f;
    float ia  = 0.5f / (astd * astd + EPSF);
    float isc = 0.5f / (sstd * sstd + EPSF);

    float a = ua[o * T_ + lane] * high_a;
    float s = us[o * T_ + lane] * s3;
    float w = expf(-(a * a * ia + s * s * isc));
    float sum = w;
    #pragma unroll
    for (int d = 16; d; d >>= 1) sum += __shfl_xor_sync(0xffffffffu, sum, d);
    float inv = 2.f / (sum + EPSF);

    if (lane < S_) {
        float oxv = ox[o], oyv = oy[o];
        float dist = sqrtf(oxv * oxv + oyv * oyv);
        float a0 = atan2f(oyv, oxv);

        float ws = w * inv;
        float nd = dist + s;
        float na = a0 + a;
        float dx = nd * cosf(na);
        float dy = nd * sinf(na);
        float fy = floorf(dy), fx = floorf(dx);
        float ay = dy - fy,  axf = dx - fx;
        int iy = max(-H_, min(H_ - 1, (int)fy));
        int ix = max(-W_, min(W_ - 1, (int)fx));
        float wy0 = 1.f - ay, wx0 = 1.f - axf;
        int key = ((iy + 256) << 10) | (ix + 256);

        int rank = 0;
        #pragma unroll
        for (int j = 0; j < S_; j++) {
            int kj = __shfl_sync(0x0000ffffu, key, j);
            rank += (kj < key) || (kj == key && j < lane);
        }
        __half2 h00 = __float2half2_rn(ws * wy0 * wx0);
        __half2 h01 = __float2half2_rn(ws * wy0 * axf);
        __half2 h10 = __float2half2_rn(ws * ay * wx0);
        __half2 h11 = __float2half2_rn(ws * ay * axf);
        g_shift[o * S_ + rank] = make_int2(iy, ix);
        g_wtsh[o * S_ + rank]  = make_uint4(h2u(h00), h2u(h01), h2u(h10), h2u(h11));
    }
}

// ---------------------------------------------------------------------------
// Kernel 2: main gather.
// Warp = 32 lanes x 2 adjacent pixels; 4 row-groups x KH=4 rows.
// Per sample-row: 1 LDG.128 (4 wf) + lane-predicated LDG.64 fixup (1 wf);
// the third column slot comes from the NEIGHBOR LANE via SHFL (even: c =
// shfl_down of next lane's pair; odd: M loaded at eb+2 carries b,c and a =
// shfl_up of prev lane's pair). Parity is a block-uniform template branch.
// Row validity: one warp-uniform interior test (samples sorted by iy).
// fp16 accumulates 4 samples, flushed to packed fp32x2 per group.
// ---------------------------------------------------------------------------
struct Row6 { unsigned a0, a1, b0, b1, c0, c1; };

template<bool FIRST>
__device__ __forceinline__ void do_taps(const Row6 R[5], uint2 hacc[4][2],
                                        __half2 w00, __half2 w01, __half2 w10, __half2 w11)
{
    #pragma unroll
    for (int kh = 0; kh < 4; kh++) {
        const Row6& Tr = R[kh];
        const Row6& Ur = R[kh + 1];
        __half2 a;
        a = FIRST ? __hmul2(u2h(Tr.a0), w00) : __hfma2(u2h(Tr.a0), w00, u2h(hacc[kh][0].x));
        a = __hfma2(u2h(Tr.b0), w01, a);
        a = __hfma2(u2h(Ur.a0), w10, a);
        a = __hfma2(u2h(Ur.b0), w11, a);
        hacc[kh][0].x = h2u(a);
        a = FIRST ? __hmul2(u2h(Tr.a1), w00) : __hfma2(u2h(Tr.a1), w00, u2h(hacc[kh][0].y));
        a = __hfma2(u2h(Tr.b1), w01, a);
        a = __hfma2(u2h(Ur.a1), w10, a);
        a = __hfma2(u2h(Ur.b1), w11, a);
        hacc[kh][0].y = h2u(a);
        a = FIRST ? __hmul2(u2h(Tr.b0), w00) : __hfma2(u2h(Tr.b0), w00, u2h(hacc[kh][1].x));
        a = __hfma2(u2h(Tr.c0), w01, a);
        a = __hfma2(u2h(Ur.b0), w10, a);
        a = __hfma2(u2h(Ur.c0), w11, a);
        hacc[kh][1].x = h2u(a);
        a = FIRST ? __hmul2(u2h(Tr.b1), w00) : __hfma2(u2h(Tr.b1), w00, u2h(hacc[kh][1].y));
        a = __hfma2(u2h(Tr.c1), w01, a);
        a = __hfma2(u2h(Ur.b1), w10, a);
        a = __hfma2(u2h(Ur.c1), w11, a);
        hacc[kh][1].y = h2u(a);
    }
}

template<bool ODD, bool FIRST, bool EDGE>
__device__ __forceinline__ void sampleT(int2 sh, uint4 wv, int wp, int hbase,
                                        const char* __restrict__ planeB,
                                        uint2 hacc[4][2], bool fix)
{
    const int eb   = (wp + sh.y) & ~1;          // own even column pair
    const int y0   = hbase + sh.x;
    const int mcol = ODD ? eb + 2 : eb;         // LDG.128 column pair
    const int ecol = ODD ? eb + 1 : eb + 2;     // boundary-lane fixup column
    const char* __restrict__ zp = (const char*)g_zero;
    const bool mv = (unsigned)mcol < (unsigned)W_;
    const bool ev = (unsigned)ecol < (unsigned)W_;

    const char* pmB;
    const char* peB;
    if (!EDGE) {   // interior: fold y0 into base; zero page tolerates +r*ROWB_
        pmB = mv ? planeB + mcol * 8 + y0 * ROWB_ : zp;
        peB = ev ? planeB + ecol * 8 + y0 * ROWB_ : zp;
    }

    Row6 R[5];
    #pragma unroll
    for (int r = 0; r < 5; r++) {
        const char *pm, *pe;
        if (EDGE) {
            int y = y0 + r;
            bool yv = (unsigned)y < (unsigned)H_;
            pm = (mv && yv) ? planeB + mcol * 8 + y * ROWB_ : zp;
            pe = (ev && yv) ? planeB + ecol * 8 + y * ROWB_ : zp;
        } else {
            pm = pmB + r * ROWB_;
            pe = peB + r * ROWB_;
        }
        uint4 M = *(const uint4*)pm;
        uint2 E = make_uint2(0u, 0u);
        if (fix) E = *(const uint2*)pe;          // 1 active lane -> 1 wavefront

        Row6 rr;
        if (ODD) {
            unsigned s0 = __shfl_up_sync(0xffffffffu, M.z, 1);
            unsigned s1 = __shfl_up_sync(0xffffffffu, M.w, 1);
            rr.a0 = fix ? E.x : s0;  rr.a1 = fix ? E.y : s1;
            rr.b0 = M.x; rr.b1 = M.y; rr.c0 = M.z; rr.c1 = M.w;
        } else {
            unsigned s0 = __shfl_down_sync(0xffffffffu, M.x, 1);
            unsigned s1 = __shfl_down_sync(0xffffffffu, M.y, 1);
            rr.a0 = M.x; rr.a1 = M.y; rr.b0 = M.z; rr.b1 = M.w;
            rr.c0 = fix ? E.x : s0;  rr.c1 = fix ? E.y : s1;
        }
        R[r] = rr;
    }
    do_taps<FIRST>(R, hacc, u2h(wv.x), u2h(wv.y), u2h(wv.z), u2h(wv.w));
}

template<bool FIRST, bool EDGE>
__device__ __forceinline__ void do_sample(int s, const int2* s_sh, const uint4* s_w,
                                          int wp, int hbase,
                                          const char* __restrict__ planeB,
                                          uint2 hacc[4][2], bool l0, bool l31)
{
    const int2  sh = s_sh[s];
    const uint4 wv = s_w[s];
    if (sh.y & 1) sampleT<true,  FIRST, EDGE>(sh, wv, wp, hbase, planeB, hacc, l0);
    else          sampleT<false, FIRST, EDGE>(sh, wv, wp, hbase, planeB, hacc, l31);
}

template<bool EDGE>
__device__ __forceinline__ void main_loop(const int2* s_sh, const uint4* s_w,
                                          int wp, int hbase,
                                          const char* __restrict__ planeB,
                                          ull facc[4][2][2], bool l0, bool l31)
{
    #pragma unroll 1
    for (int sp = 0; sp < S_; sp += 4) {
        uint2 hacc[4][2];
        do_sample<true,  EDGE>(sp,     s_sh, s_w, wp, hbase, planeB, hacc, l0, l31);
        do_sample<false, EDGE>(sp + 1, s_sh, s_w, wp, hbase, planeB, hacc, l0, l31);
        do_sample<false, EDGE>(sp + 2, s_sh, s_w, wp, hbase, planeB, hacc, l0, l31);
        do_sample<false, EDGE>(sp + 3, s_sh, s_w, wp, hbase, planeB, hacc, l0, l31);
        #pragma unroll
        for (int kh = 0; kh < 4; kh++)
            #pragma unroll
            for (int g = 0; g < 2; g++) {
                add2(facc[kh][g][0], h2f2(hacc[kh][g].x));
                add2(facc[kh][g][1], h2f2(hacc[kh][g].y));
            }
    }
}

__global__ void __launch_bounds__(256, 2) disp_kernel(float* __restrict__ out)
{
    __shared__ int2  s_sh[S_];
    __shared__ uint4 s_w[S_];
    const int tid = threadIdx.x;
    const int o = blockIdx.y, b = blockIdx.z;
    const int bo = b * O_ + o;
    if (tid < S_) { s_sh[tid] = g_shift[o * S_ + tid]; s_w[tid] = g_wtsh[o * S_ + tid]; }
    __syncthreads();

    const int lane = tid & 31, warp = tid >> 5;
    const int half = warp & 1, hy = warp >> 1;
    const int hbase = blockIdx.x * 16 + hy * 4;
    const int wp = half * 64 + lane * 2;
    const bool l0 = (lane == 0), l31 = (lane == 31);
    const char* __restrict__ planeB =
        (const char*)(g_xT4 + (size_t)bo * (HW_ / 2));

    ull facc[4][2][2];
    #pragma unroll
    for (int i = 0; i < 4; i++)
        #pragma unroll
        for (int g = 0; g < 2; g++) { facc[i][g][0] = 0ull; facc[i][g][1] = 0ull; }

    // samples sorted by iy: s_sh[0].x = min, s_sh[S_-1].x = max (warp-uniform)
    const bool interior = (hbase + s_sh[0].x >= 0) && (hbase + s_sh[S_ - 1].x <= H_ - 5);

    if (interior) main_loop<false>(s_sh, s_w, wp, hbase, planeB, facc, l0, l31);
    else          main_loop<true >(s_sh, s_w, wp, hbase, planeB, facc, l0, l31);

    float* __restrict__ ob = out + (size_t)bo * CPO_ * HW_;
    #pragma unroll
    for (int kh = 0; kh < 4; kh++) {
        const int h = hbase + kh;
        float p0[4], p1[4];
        unpk(facc[kh][0][0], p0[0], p0[1]);
        unpk(facc[kh][0][1], p0[2], p0[3]);
        unpk(facc[kh][1][0], p1[0], p1[1]);
        unpk(facc[kh][1][1], p1[2], p1[3]);
        #pragma unroll
        for (int c = 0; c < 4; c++) {
            float2 v = make_float2(p0[c], p1[c]);
            *reinterpret_cast<float2*>(ob + (size_t)c * HW_ + (size_t)h * W_ + wp) = v;
        }
    }
}

extern "C" void kernel_launch(void* const* d_in, const int* in_sizes, int n_in,
                              void* d_out, int out_size)
{
    const float* x  = (const float*)d_in[0];
    const float* ox = (const float*)d_in[1];
    const float* oy = (const float*)d_in[2];
    const float* ua = (const float*)d_in[3];
    const float* us = (const float*)d_in[4];
    const float* ar = (const float*)d_in[5];
    const float* sr = (const float*)d_in[6];
    float* out = (float*)d_out;

    pre_kernel<<<NT_ + O_/8, 256>>>(x, ox, oy, ua, us, ar, sr);
    disp_kernel<<<dim3(H_ / 16, O_, B_), 256>>>(out);
}

// round 9
// speedup vs baseline: 1.2462x; 1.2462x over previous
#include <cuda_runtime.h>
#include <cuda_fp16.h>

#define B_ 16
#define O_ 32
#define CPO_ 4
#define H_ 128
#define W_ 128
#define S_ 16
#define T_ 32
#define HW_ (H_*W_)
#define NT_ ((B_*O_*H_*W_/4)/256)   /* transpose blocks = 8192 */
#define ROWB_ (W_/2*16)             /* bytes per scratch row = 1024 */

typedef unsigned long long ull;

// Scratch: transposed input, (B,O,H,W/2) uint4 = 2 adjacent pixels x 4ch fp16.
__device__ uint4 g_xT4[(size_t)B_ * O_ * H_ * W_ / 2];
__device__ int2  g_shift[O_ * S_];
__device__ uint4 g_wtsh[O_ * S_];
// Zero page: OOB loads redirect here (fast path reads up to 4*1024+16 bytes).
__device__ uint4 g_zero[4 * 64 + 8];   // zero-initialized by definition

// ---------------------------------------------------------------------------
// packed helpers
// ---------------------------------------------------------------------------
__device__ __forceinline__ void add2(ull& d, ull v) {
    asm("add.rn.f32x2 %0,%0,%1;" : "+l"(d) : "l"(v));
}
__device__ __forceinline__ void unpk(ull v, float& lo, float& hi) {
    asm("mov.b64 {%0,%1},%2;" : "=f"(lo), "=f"(hi) : "l"(v));
}
__device__ __forceinline__ ull h2f2(unsigned u) {
    ull r;
    asm("{\n\t.reg .b16 a,b;\n\t.reg .f32 lo,hi;\n\t"
        "mov.b32 {a,b},%1;\n\tcvt.f32.f16 lo,a;\n\tcvt.f32.f16 hi,b;\n\t"
        "mov.b64 %0,{lo,hi};\n\t}" : "=l"(r) : "r"(u));
    return r;
}
__device__ __forceinline__ __half2 u2h(unsigned u) {
    return *reinterpret_cast<__half2*>(&u);
}
__device__ __forceinline__ unsigned h2u(__half2 h) {
    return *reinterpret_cast<unsigned*>(&h);
}

// ---------------------------------------------------------------------------
// Kernel 1 (fused): blocks [0,NT_) transpose, blocks [NT_,NT_+4) params.
// ---------------------------------------------------------------------------
__global__ void pre_kernel(const float* __restrict__ x,
                           const float* __restrict__ ox, const float* __restrict__ oy,
                           const float* __restrict__ ua, const float* __restrict__ us,
                           const float* __restrict__ ar, const float* __restrict__ sr)
{
    if (blockIdx.x < NT_) {
        int idx  = blockIdx.x * 256 + threadIdx.x;      // pixel-group of 4
        int wg   = idx & (W_/4 - 1);
        int rest = idx >> 5;                            // bo*H + h
        size_t base = ((size_t)(rest >> 7) * CPO_ * H_ + (rest & (H_-1))) * W_ + wg * 4;

        float4 c0 = *(const float4*)(x + base);
        float4 c1 = *(const float4*)(x + base + HW_);
        float4 c2 = *(const float4*)(x + base + 2 * HW_);
        float4 c3 = *(const float4*)(x + base + 3 * HW_);

        uint4 o0, o1;
        __half2 h;
        h = __floats2half2_rn(c0.x, c1.x); o0.x = h2u(h);
        h = __floats2half2_rn(c2.x, c3.x); o0.y = h2u(h);
        h = __floats2half2_rn(c0.y, c1.y); o0.z = h2u(h);
        h = __floats2half2_rn(c2.y, c3.y); o0.w = h2u(h);
        h = __floats2half2_rn(c0.z, c1.z); o1.x = h2u(h);
        h = __floats2half2_rn(c2.z, c3.z); o1.y = h2u(h);
        h = __floats2half2_rn(c0.w, c1.w); o1.z = h2u(h);
        h = __floats2half2_rn(c2.w, c3.w); o1.w = h2u(h);

        g_xT4[(size_t)idx * 2]     = o0;
        g_xT4[(size_t)idx * 2 + 1] = o1;
        return;
    }

    // ---- param path ----
    const int lane = threadIdx.x & 31;
    const int o    = (blockIdx.x - NT_) * 8 + (threadIdx.x >> 5);
    const float MINA = 0.024979197860971382f;
    const float PIF  = 3.14159265358979323846f;
    const float EPSF = 1.1920928955078125e-07f;

    float astd = 1.f / (1.f + expf(-ar[o])) * (PIF - MINA) + MINA;
    float sstd = 1.f / (1.f + expf(-sr[o])) * (5.0f - 0.2f) + 0.2f;
    float high_a = fminf(astd * 3.f, PIF);
    float s3 = sstd * 3.f;
    float ia  = 0.5f / (astd * astd + EPSF);
    float isc = 0.5f / (sstd * sstd + EPSF);

    float a = ua[o * T_ + lane] * high_a;
    float s = us[o * T_ + lane] * s3;
    float w = expf(-(a * a * ia + s * s * isc));
    float sum = w;
    #pragma unroll
    for (int d = 16; d; d >>= 1) sum += __shfl_xor_sync(0xffffffffu, sum, d);
    float inv = 2.f / (sum + EPSF);

    if (lane < S_) {
        float oxv = ox[o], oyv = oy[o];
        float dist = sqrtf(oxv * oxv + oyv * oyv);
        float a0 = atan2f(oyv, oxv);

        float ws = w * inv;
        float nd = dist + s;
        float na = a0 + a;
        float dx = nd * cosf(na);
        float dy = nd * sinf(na);
        float fy = floorf(dy), fx = floorf(dx);
        float ay = dy - fy,  axf = dx - fx;
        int iy = max(-H_, min(H_ - 1, (int)fy));
        int ix = max(-W_, min(W_ - 1, (int)fx));
        float wy0 = 1.f - ay, wx0 = 1.f - axf;
        int key = ((iy + 256) << 10) | (ix + 256);

        int rank = 0;
        #pragma unroll
        for (int j = 0; j < S_; j++) {
            int kj = __shfl_sync(0x0000ffffu, key, j);
            rank += (kj < key) || (kj == key && j < lane);
        }
        __half2 h00 = __float2half2_rn(ws * wy0 * wx0);
        __half2 h01 = __float2half2_rn(ws * wy0 * axf);
        __half2 h10 = __float2half2_rn(ws * ay * wx0);
        __half2 h11 = __float2half2_rn(ws * ay * axf);
        g_shift[o * S_ + rank] = make_int2(iy, ix);
        g_wtsh[o * S_ + rank]  = make_uint4(h2u(h00), h2u(h01), h2u(h10), h2u(h11));
    }
}

// ---------------------------------------------------------------------------
// Kernel 2: main gather (R6 datapath, 128-thread CTAs for occupancy).
// Block = 128 threads = 4 warps = 4 h-groups; W is split across 2 blocks.
// Warp = 32 lanes x 2 adjacent pixels, KH=4 rows.
// Per sample-row: 1 LDG.128 + 1 LDG.64 (the 3 consumed column slots); parity
// via block-uniform template branch; OOB columns/rows redirect to zero page.
// fp16 accumulates 4 samples, flushed to packed fp32x2 per group.
// ---------------------------------------------------------------------------
struct Row6 { unsigned a0, a1, b0, b1, c0, c1; };

template<bool FIRST>
__device__ __forceinline__ void do_taps(const Row6 R[5], uint2 hacc[4][2],
                                        __half2 w00, __half2 w01, __half2 w10, __half2 w11)
{
    #pragma unroll
    for (int kh = 0; kh < 4; kh++) {
        const Row6& Tr = R[kh];
        const Row6& Ur = R[kh + 1];
        __half2 a;
        a = FIRST ? __hmul2(u2h(Tr.a0), w00) : __hfma2(u2h(Tr.a0), w00, u2h(hacc[kh][0].x));
        a = __hfma2(u2h(Tr.b0), w01, a);
        a = __hfma2(u2h(Ur.a0), w10, a);
        a = __hfma2(u2h(Ur.b0), w11, a);
        hacc[kh][0].x = h2u(a);
        a = FIRST ? __hmul2(u2h(Tr.a1), w00) : __hfma2(u2h(Tr.a1), w00, u2h(hacc[kh][0].y));
        a = __hfma2(u2h(Tr.b1), w01, a);
        a = __hfma2(u2h(Ur.a1), w10, a);
        a = __hfma2(u2h(Ur.b1), w11, a);
        hacc[kh][0].y = h2u(a);
        a = FIRST ? __hmul2(u2h(Tr.b0), w00) : __hfma2(u2h(Tr.b0), w00, u2h(hacc[kh][1].x));
        a = __hfma2(u2h(Tr.c0), w01, a);
        a = __hfma2(u2h(Ur.b0), w10, a);
        a = __hfma2(u2h(Ur.c0), w11, a);
        hacc[kh][1].x = h2u(a);
        a = FIRST ? __hmul2(u2h(Tr.b1), w00) : __hfma2(u2h(Tr.b1), w00, u2h(hacc[kh][1].y));
        a = __hfma2(u2h(Tr.c1), w01, a);
        a = __hfma2(u2h(Ur.b1), w10, a);
        a = __hfma2(u2h(Ur.c1), w11, a);
        hacc[kh][1].y = h2u(a);
    }
}

template<bool ODD>
__device__ __forceinline__ Row6 mapRow(uint4 A, uint2 Bv)
{
    Row6 r;
    if (ODD) { r.a0 = Bv.x; r.a1 = Bv.y; r.b0 = A.x; r.b1 = A.y; r.c0 = A.z; r.c1 = A.w; }
    else     { r.a0 = A.x;  r.a1 = A.y;  r.b0 = A.z; r.b1 = A.w; r.c0 = Bv.x; r.c1 = Bv.y; }
    return r;
}

template<bool ODD, bool FIRST>
__device__ __forceinline__ void do_sample_t(int2 sh, uint4 wv,
                                            int wp, int hbase,
                                            const char* __restrict__ planeB,
                                            uint2 hacc[4][2])
{
    const __half2 w00 = u2h(wv.x), w01 = u2h(wv.y), w10 = u2h(wv.z), w11 = u2h(wv.w);
    const int eb = (wp + sh.y) & ~1;
    const int y0 = hbase + sh.x;
    const bool q0 = (unsigned)eb       < (unsigned)W_;
    const bool q1 = (unsigned)(eb + 2) < (unsigned)W_;
    const char* __restrict__ zp = (const char*)g_zero;
    const char* cb = planeB + eb * 8;               // (eb/2)*16
    const bool  q4 = ODD ? q1 : q0;
    const bool  q2 = ODD ? q0 : q1;
    const int   o4 = ODD ? 16 : 0;
    const int   o2 = ODD ? 8  : 16;

    Row6 R[5];
    if (y0 >= 0 && y0 <= H_ - 5) {                  // warp-uniform fast path
        const char* p4 = q4 ? cb + y0 * ROWB_ + o4 : zp;
        const char* p2 = q2 ? cb + y0 * ROWB_ + o2 : zp;
        #pragma unroll
        for (int r = 0; r < 5; r++) {
            uint4 A  = *(const uint4*)(p4 + r * ROWB_);
            uint2 Bv = *(const uint2*)(p2 + r * ROWB_);
            R[r] = mapRow<ODD>(A, Bv);
        }
    } else {                                         // edge windows
        #pragma unroll
        for (int r = 0; r < 5; r++) {
            int y = y0 + r;
            bool yv = (unsigned)y < (unsigned)H_;
            const char* p4 = (q4 && yv) ? cb + y * ROWB_ + o4 : zp;
            const char* p2 = (q2 && yv) ? cb + y * ROWB_ + o2 : zp;
            uint4 A  = *(const uint4*)p4;
            uint2 Bv = *(const uint2*)p2;
            R[r] = mapRow<ODD>(A, Bv);
        }
    }
    do_taps<FIRST>(R, hacc, w00, w01, w10, w11);
}

template<bool FIRST>
__device__ __forceinline__ void do_sample(int s, const int2* s_sh, const uint4* s_w,
                                          int wp, int hbase,
                                          const char* __restrict__ planeB,
                                          uint2 hacc[4][2])
{
    const int2  sh = s_sh[s];
    const uint4 wv = s_w[s];
    if (sh.y & 1) do_sample_t<true,  FIRST>(sh, wv, wp, hbase, planeB, hacc);
    else          do_sample_t<false, FIRST>(sh, wv, wp, hbase, planeB, hacc);
}

__global__ void __launch_bounds__(128, 5) disp_kernel(float* __restrict__ out)
{
    __shared__ int2  s_sh[S_];
    __shared__ uint4 s_w[S_];
    const int tid = threadIdx.x;
    const int o = blockIdx.y, b = blockIdx.z;
    const int bo = b * O_ + o;
    if (tid < S_) { s_sh[tid] = g_shift[o * S_ + tid]; s_w[tid] = g_wtsh[o * S_ + tid]; }
    __syncthreads();

    const int lane = tid & 31, warp = tid >> 5;
    const int hblk = blockIdx.x >> 1, wblk = blockIdx.x & 1;
    const int hbase = hblk * 16 + warp * 4;
    const int wp = wblk * 64 + lane * 2;
    const char* __restrict__ planeB =
        (const char*)(g_xT4 + (size_t)bo * (HW_ / 2));

    ull facc[4][2][2];
    #pragma unroll
    for (int i = 0; i < 4; i++)
        #pragma unroll
        for (int g = 0; g < 2; g++) { facc[i][g][0] = 0ull; facc[i][g][1] = 0ull; }

    #pragma unroll 1
    for (int sp = 0; sp < S_; sp += 4) {
        uint2 hacc[4][2];
        do_sample<true >(sp,     s_sh, s_w, wp, hbase, planeB, hacc);
        do_sample<false>(sp + 1, s_sh, s_w, wp, hbase, planeB, hacc);
        do_sample<false>(sp + 2, s_sh, s_w, wp, hbase, planeB, hacc);
        do_sample<false>(sp + 3, s_sh, s_w, wp, hbase, planeB, hacc);
        #pragma unroll
        for (int kh = 0; kh < 4; kh++)
            #pragma unroll
            for (int g = 0; g < 2; g++) {
                add2(facc[kh][g][0], h2f2(hacc[kh][g].x));
                add2(facc[kh][g][1], h2f2(hacc[kh][g].y));
            }
    }

    float* __restrict__ ob = out + (size_t)bo * CPO_ * HW_;
    #pragma unroll
    for (int kh = 0; kh < 4; kh++) {
        const int h = hbase + kh;
        float p0[4], p1[4];
        unpk(facc[kh][0][0], p0[0], p0[1]);
        unpk(facc[kh][0][1], p0[2], p0[3]);
        unpk(facc[kh][1][0], p1[0], p1[1]);
        unpk(facc[kh][1][1], p1[2], p1[3]);
        #pragma unroll
        for (int c = 0; c < 4; c++) {
            float2 v = make_float2(p0[c], p1[c]);
            *reinterpret_cast<float2*>(ob + (size_t)c * HW_ + (size_t)h * W_ + wp) = v;
        }
    }
}

extern "C" void kernel_launch(void* const* d_in, const int* in_sizes, int n_in,
                              void* d_out, int out_size)
{
    const float* x  = (const float*)d_in[0];
    const float* ox = (const float*)d_in[1];
    const float* oy = (const float*)d_in[2];
    const float* ua = (const float*)d_in[3];
    const float* us = (const float*)d_in[4];
    const float* ar = (const float*)d_in[5];
    const float* sr = (const float*)d_in[6];
    float* out = (float*)d_out;

    pre_kernel<<<NT_ + O_/8, 256>>>(x, ox, oy, ua, us, ar, sr);
    disp_kernel<<<dim3((H_/16) * (W_/64), O_, B_), 128>>>(out);
}

// round 10
// speedup vs baseline: 1.2468x; 1.0005x over previous
#include <cuda_runtime.h>
#include <cuda_fp16.h>

#define B_ 16
#define O_ 32
#define CPO_ 4
#define H_ 128
#define W_ 128
#define S_ 16
#define T_ 32
#define HW_ (H_*W_)
#define NT_ ((B_*O_*H_*W_/4)/256)   /* transpose blocks = 8192 */
#define ROWB_ (W_/2*16)             /* bytes per scratch row = 1024 */

typedef unsigned long long ull;

// Scratch: transposed input, (B,O,H,W/2) uint4 = 2 adjacent pixels x 4ch fp16.
__device__ uint4 g_xT4[(size_t)B_ * O_ * H_ * W_ / 2];
__device__ int2  g_shift[O_ * S_];
__device__ uint4 g_wtsh[O_ * S_];
// Zero page: OOB loads redirect here (fast path reads up to 4*1024+16 bytes).
__device__ uint4 g_zero[4 * 64 + 8];   // zero-initialized by definition

// ---------------------------------------------------------------------------
// packed helpers
// ---------------------------------------------------------------------------
__device__ __forceinline__ void add2(ull& d, ull v) {
    asm("add.rn.f32x2 %0,%0,%1;" : "+l"(d) : "l"(v));
}
__device__ __forceinline__ void unpk(ull v, float& lo, float& hi) {
    asm("mov.b64 {%0,%1},%2;" : "=f"(lo), "=f"(hi) : "l"(v));
}
__device__ __forceinline__ ull h2f2(unsigned u) {
    ull r;
    asm("{\n\t.reg .b16 a,b;\n\t.reg .f32 lo,hi;\n\t"
        "mov.b32 {a,b},%1;\n\tcvt.f32.f16 lo,a;\n\tcvt.f32.f16 hi,b;\n\t"
        "mov.b64 %0,{lo,hi};\n\t}" : "=l"(r) : "r"(u));
    return r;
}
__device__ __forceinline__ __half2 u2h(unsigned u) {
    return *reinterpret_cast<__half2*>(&u);
}
__device__ __forceinline__ unsigned h2u(__half2 h) {
    return *reinterpret_cast<unsigned*>(&h);
}

// ---------------------------------------------------------------------------
// Kernel 1 (fused): blocks [0,NT_) transpose, blocks [NT_,NT_+4) params.
// ---------------------------------------------------------------------------
__global__ void pre_kernel(const float* __restrict__ x,
                           const float* __restrict__ ox, const float* __restrict__ oy,
                           const float* __restrict__ ua, const float* __restrict__ us,
                           const float* __restrict__ ar, const float* __restrict__ sr)
{
    if (blockIdx.x < NT_) {
        int idx  = blockIdx.x * 256 + threadIdx.x;      // pixel-group of 4
        int wg   = idx & (W_/4 - 1);
        int rest = idx >> 5;                            // bo*H + h
        size_t base = ((size_t)(rest >> 7) * CPO_ * H_ + (rest & (H_-1))) * W_ + wg * 4;

        float4 c0 = *(const float4*)(x + base);
        float4 c1 = *(const float4*)(x + base + HW_);
        float4 c2 = *(const float4*)(x + base + 2 * HW_);
        float4 c3 = *(const float4*)(x + base + 3 * HW_);

        uint4 o0, o1;
        __half2 h;
        h = __floats2half2_rn(c0.x, c1.x); o0.x = h2u(h);
        h = __floats2half2_rn(c2.x, c3.x); o0.y = h2u(h);
        h = __floats2half2_rn(c0.y, c1.y); o0.z = h2u(h);
        h = __floats2half2_rn(c2.y, c3.y); o0.w = h2u(h);
        h = __floats2half2_rn(c0.z, c1.z); o1.x = h2u(h);
        h = __floats2half2_rn(c2.z, c3.z); o1.y = h2u(h);
        h = __floats2half2_rn(c0.w, c1.w); o1.z = h2u(h);
        h = __floats2half2_rn(c2.w, c3.w); o1.w = h2u(h);

        g_xT4[(size_t)idx * 2]     = o0;
        g_xT4[(size_t)idx * 2 + 1] = o1;
        return;
    }

    // ---- param path ----
    const int lane = threadIdx.x & 31;
    const int o    = (blockIdx.x - NT_) * 8 + (threadIdx.x >> 5);
    const float MINA = 0.024979197860971382f;
    const float PIF  = 3.14159265358979323846f;
    const float EPSF = 1.1920928955078125e-07f;

    float astd = 1.f / (1.f + expf(-ar[o])) * (PIF - MINA) + MINA;
    float sstd = 1.f / (1.f + expf(-sr[o])) * (5.0f - 0.2f) + 0.2f;
    float high_a = fminf(astd * 3.f, PIF);
    float s3 = sstd * 3.f;
    float ia  = 0.5f / (astd * astd + EPSF);
    float isc = 0.5f / (sstd * sstd + EPSF);

    float a = ua[o * T_ + lane] * high_a;
    float s = us[o * T_ + lane] * s3;
    float w = expf(-(a * a * ia + s * s * isc));
    float sum = w;
    #pragma unroll
    for (int d = 16; d; d >>= 1) sum += __shfl_xor_sync(0xffffffffu, sum, d);
    float inv = 2.f / (sum + EPSF);

    if (lane < S_) {
        float oxv = ox[o], oyv = oy[o];
        float dist = sqrtf(oxv * oxv + oyv * oyv);
        float a0 = atan2f(oyv, oxv);

        float ws = w * inv;
        float nd = dist + s;
        float na = a0 + a;
        float dx = nd * cosf(na);
        float dy = nd * sinf(na);
        float fy = floorf(dy), fx = floorf(dx);
        float ay = dy - fy,  axf = dx - fx;
        int iy = max(-H_, min(H_ - 1, (int)fy));
        int ix = max(-W_, min(W_ - 1, (int)fx));
        float wy0 = 1.f - ay, wx0 = 1.f - axf;
        int key = ((iy + 256) << 10) | (ix + 256);

        int rank = 0;
        #pragma unroll
        for (int j = 0; j < S_; j++) {
            int kj = __shfl_sync(0x0000ffffu, key, j);
            rank += (kj < key) || (kj == key && j < lane);
        }
        __half2 h00 = __float2half2_rn(ws * wy0 * wx0);
        __half2 h01 = __float2half2_rn(ws * wy0 * axf);
        __half2 h10 = __float2half2_rn(ws * ay * wx0);
        __half2 h11 = __float2half2_rn(ws * ay * axf);
        g_shift[o * S_ + rank] = make_int2(iy, ix);
        g_wtsh[o * S_ + rank]  = make_uint4(h2u(h00), h2u(h01), h2u(h10), h2u(h11));
    }
}

// ---------------------------------------------------------------------------
// Kernel 2: main gather (R9 datapath + rolling 2-row window for occupancy).
// Block = 128 threads = 4 warps = 4 h-groups; W split across 2 blocks.
// Warp = 32 lanes x 2 adjacent pixels, KH=4 rows.
// Per sample-row: 1 LDG.128 + 1 LDG.64; parity via block-uniform template;
// OOB columns/rows redirect to zero page. Consecutive row pairs feed one kh
// each, so only 2 rows stay live (rolling) -> fewer regs -> 6 CTAs/SM.
// fp16 accumulates 4 samples, flushed to packed fp32x2 per group.
// ---------------------------------------------------------------------------
struct Row6 { unsigned a0, a1, b0, b1, c0, c1; };

template<bool ODD>
__device__ __forceinline__ Row6 mapRow(uint4 A, uint2 Bv)
{
    Row6 r;
    if (ODD) { r.a0 = Bv.x; r.a1 = Bv.y; r.b0 = A.x; r.b1 = A.y; r.c0 = A.z; r.c1 = A.w; }
    else     { r.a0 = A.x;  r.a1 = A.y;  r.b0 = A.z; r.b1 = A.w; r.c0 = Bv.x; r.c1 = Bv.y; }
    return r;
}

// taps for ONE output row kh, from top row Tr and bottom row Ur
template<bool FIRST>
__device__ __forceinline__ void tap_row(const Row6& Tr, const Row6& Ur,
                                        uint2& h0, uint2& h1,
                                        __half2 w00, __half2 w01, __half2 w10, __half2 w11)
{
    __half2 a;
    a = FIRST ? __hmul2(u2h(Tr.a0), w00) : __hfma2(u2h(Tr.a0), w00, u2h(h0.x));
    a = __hfma2(u2h(Tr.b0), w01, a);
    a = __hfma2(u2h(Ur.a0), w10, a);
    a = __hfma2(u2h(Ur.b0), w11, a);
    h0.x = h2u(a);
    a = FIRST ? __hmul2(u2h(Tr.a1), w00) : __hfma2(u2h(Tr.a1), w00, u2h(h0.y));
    a = __hfma2(u2h(Tr.b1), w01, a);
    a = __hfma2(u2h(Ur.a1), w10, a);
    a = __hfma2(u2h(Ur.b1), w11, a);
    h0.y = h2u(a);
    a = FIRST ? __hmul2(u2h(Tr.b0), w00) : __hfma2(u2h(Tr.b0), w00, u2h(h1.x));
    a = __hfma2(u2h(Tr.c0), w01, a);
    a = __hfma2(u2h(Ur.b0), w10, a);
    a = __hfma2(u2h(Ur.c0), w11, a);
    h1.x = h2u(a);
    a = FIRST ? __hmul2(u2h(Tr.b1), w00) : __hfma2(u2h(Tr.b1), w00, u2h(h1.y));
    a = __hfma2(u2h(Tr.c1), w01, a);
    a = __hfma2(u2h(Ur.b1), w10, a);
    a = __hfma2(u2h(Ur.c1), w11, a);
    h1.y = h2u(a);
}

template<bool ODD, bool FIRST>
__device__ __forceinline__ void do_sample_t(int2 sh, uint4 wv,
                                            int wp, int hbase,
                                            const char* __restrict__ planeB,
                                            uint2 hacc[4][2])
{
    const __half2 w00 = u2h(wv.x), w01 = u2h(wv.y), w10 = u2h(wv.z), w11 = u2h(wv.w);
    const int eb = (wp + sh.y) & ~1;
    const int y0 = hbase + sh.x;
    const bool q0 = (unsigned)eb       < (unsigned)W_;
    const bool q1 = (unsigned)(eb + 2) < (unsigned)W_;
    const char* __restrict__ zp = (const char*)g_zero;
    const char* cb = planeB + eb * 8;               // (eb/2)*16
    const bool  q4 = ODD ? q1 : q0;
    const bool  q2 = ODD ? q0 : q1;
    const int   o4 = ODD ? 16 : 0;
    const int   o2 = ODD ? 8  : 16;

    if (y0 >= 0 && y0 <= H_ - 5) {                  // warp-uniform fast path
        const char* p4 = q4 ? cb + y0 * ROWB_ + o4 : zp;
        const char* p2 = q2 ? cb + y0 * ROWB_ + o2 : zp;
        Row6 P = mapRow<ODD>(*(const uint4*)p4, *(const uint2*)p2);
        #pragma unroll
        for (int r = 1; r <= 4; r++) {
            Row6 C = mapRow<ODD>(*(const uint4*)(p4 + r * ROWB_),
                                 *(const uint2*)(p2 + r * ROWB_));
            tap_row<FIRST>(P, C, hacc[r-1][0], hacc[r-1][1], w00, w01, w10, w11);
            P = C;
        }
    } else {                                         // edge windows
        const char* p4 = (q4 && (unsigned)y0 < (unsigned)H_) ? cb + y0 * ROWB_ + o4 : zp;
        const char* p2 = (q2 && (unsigned)y0 < (unsigned)H_) ? cb + y0 * ROWB_ + o2 : zp;
        Row6 P = mapRow<ODD>(*(const uint4*)p4, *(const uint2*)p2);
        #pragma unroll
        for (int r = 1; r <= 4; r++) {
            int y = y0 + r;
            bool yv = (unsigned)y < (unsigned)H_;
            const char* q4p = (q4 && yv) ? cb + y * ROWB_ + o4 : zp;
            const char* q2p = (q2 && yv) ? cb + y * ROWB_ + o2 : zp;
            Row6 C = mapRow<ODD>(*(const uint4*)q4p, *(const uint2*)q2p);
            tap_row<FIRST>(P, C, hacc[r-1][0], hacc[r-1][1], w00, w01, w10, w11);
            P = C;
        }
    }
}

template<bool FIRST>
__device__ __forceinline__ void do_sample(int s, const int2* s_sh, const uint4* s_w,
                                          int wp, int hbase,
                                          const char* __restrict__ planeB,
                                          uint2 hacc[4][2])
{
    const int2  sh = s_sh[s];
    const uint4 wv = s_w[s];
    if (sh.y & 1) do_sample_t<true,  FIRST>(sh, wv, wp, hbase, planeB, hacc);
    else          do_sample_t<false, FIRST>(sh, wv, wp, hbase, planeB, hacc);
}

__global__ void __launch_bounds__(128, 6) disp_kernel(float* __restrict__ out)
{
    __shared__ int2  s_sh[S_];
    __shared__ uint4 s_w[S_];
    const int tid = threadIdx.x;
    const int o = blockIdx.y, b = blockIdx.z;
    const int bo = b * O_ + o;
    if (tid < S_) { s_sh[tid] = g_shift[o * S_ + tid]; s_w[tid] = g_wtsh[o * S_ + tid]; }
    __syncthreads();

    const int lane = tid & 31, warp = tid >> 5;
    const int hblk = blockIdx.x >> 1, wblk = blockIdx.x & 1;
    const int hbase = hblk * 16 + warp * 4;
    const int wp = wblk * 64 + lane * 2;
    const char* __restrict__ planeB =
        (const char*)(g_xT4 + (size_t)bo * (HW_ / 2));

    ull facc[4][2][2];
    #pragma unroll
    for (int i = 0; i < 4; i++)
        #pragma unroll
        for (int g = 0; g < 2; g++) { facc[i][g][0] = 0ull; facc[i][g][1] = 0ull; }

    #pragma unroll 1
    for (int sp = 0; sp < S_; sp += 4) {
        uint2 hacc[4][2];
        do_sample<true >(sp,     s_sh, s_w, wp, hbase, planeB, hacc);
        do_sample<false>(sp + 1, s_sh, s_w, wp, hbase, planeB, hacc);
        do_sample<false>(sp + 2, s_sh, s_w, wp, hbase, planeB, hacc);
        do_sample<false>(sp + 3, s_sh, s_w, wp, hbase, planeB, hacc);
        #pragma unroll
        for (int kh = 0; kh < 4; kh++)
            #pragma unroll
            for (int g = 0; g < 2; g++) {
                add2(facc[kh][g][0], h2f2(hacc[kh][g].x));
                add2(facc[kh][g][1], h2f2(hacc[kh][g].y));
            }
    }

    float* __restrict__ ob = out + (size_t)bo * CPO_ * HW_;
    #pragma unroll
    for (int kh = 0; kh < 4; kh++) {
        const int h = hbase + kh;
        float p0[4], p1[4];
        unpk(facc[kh][0][0], p0[0], p0[1]);
        unpk(facc[kh][0][1], p0[2], p0[3]);
        unpk(facc[kh][1][0], p1[0], p1[1]);
        unpk(facc[kh][1][1], p1[2], p1[3]);
        #pragma unroll
        for (int c = 0; c < 4; c++) {
            float2 v = make_float2(p0[c], p1[c]);
            *reinterpret_cast<float2*>(ob + (size_t)c * HW_ + (size_t)h * W_ + wp) = v;
        }
    }
}

extern "C" void kernel_launch(void* const* d_in, const int* in_sizes, int n_in,
                              void* d_out, int out_size)
{
    const float* x  = (const float*)d_in[0];
    const float* ox = (const float*)d_in[1];
    const float* oy = (const float*)d_in[2];
    const float* ua = (const float*)d_in[3];
    const float* us = (const float*)d_in[4];
    const float* ar = (const float*)d_in[5];
    const float* sr = (const float*)d_in[6];
    float* out = (float*)d_out;

    pre_kernel<<<NT_ + O_/8, 256>>>(x, ox, oy, ua, us, ar, sr);
    disp_kernel<<<dim3((H_/16) * (W_/64), O_, B_), 128>>>(out);
}